// round 5
// baseline (speedup 1.0000x reference)
#include <cuda_runtime.h>
#include <math.h>

#define D 8192
#define M_TIME 16
#define KWTA_K (D / 8)
#define ROWS 8
#define GTHREADS 256
#define CHUNK 1024                  // floats per row per stage
#define C4 (CHUNK / 4)              // 256 float4 per row per stage == GTHREADS
#define NCHUNK (D / CHUNK)          // 8
#define STAGE_F4 (ROWS * C4)        // 2048 float4 per stage (32 KB)
#define SMEM_BYTES (2 * STAGE_F4 * 16)   // 64 KB double buffer

// Scratch (device globals — no allocation allowed)
__device__ float g_x[D];
__device__ float g_rpre[D];
__device__ float g_k[D];
__device__ float g_v[D];
__device__ float g_y[D];
__device__ float g_h[D];

__device__ __forceinline__ float softplusf(float x) {
    if (x > 20.f) return x;
    if (x < -20.f) return expf(x);
    return log1pf(expf(x));
}

__device__ __forceinline__ void cp_async16(void* smem_dst, const void* gmem_src) {
    unsigned saddr = (unsigned)__cvta_generic_to_shared(smem_dst);
    asm volatile("cp.async.cg.shared.global [%0], [%1], 16;\n"
                 :: "r"(saddr), "l"(gmem_src));
}
__device__ __forceinline__ void cp_commit() {
    asm volatile("cp.async.commit_group;\n");
}
template <int N>
__device__ __forceinline__ void cp_wait() {
    asm volatile("cp.async.wait_group %0;\n" :: "n"(N));
}

// ---------------------------------------------------------------------------
// K0: x = rmsnorm(x_in + pred) * g_norm     (1 block, 1024 threads)
// ---------------------------------------------------------------------------
__global__ void rmsnorm_kernel(const float* __restrict__ x_in,
                               const float* __restrict__ pred,
                               const float* __restrict__ g_norm) {
    __shared__ float red[1024];
    float s = 0.f;
    for (int i = threadIdx.x; i < D; i += 1024) {
        float t = x_in[i] + pred[i];
        s += t * t;
    }
    red[threadIdx.x] = s;
    __syncthreads();
    for (int o = 512; o > 0; o >>= 1) {
        if (threadIdx.x < o) red[threadIdx.x] += red[threadIdx.x + o];
        __syncthreads();
    }
    float scale = rsqrtf(red[0] / (float)D + 1e-6f);
    for (int i = threadIdx.x; i < D; i += 1024) {
        g_x[i] = (x_in[i] + pred[i]) * scale * g_norm[i];
    }
}

// ---------------------------------------------------------------------------
// Barrier-free GEMV pipeline, R3 layout:
//   thread t owns float4 column-slot t of every row in every chunk.
//   It writes (cp.async) and reads (LDS) ONLY its own slots, so per-thread
//   cp.async.wait_group is the only sync needed. x is register-cached.
// ---------------------------------------------------------------------------
__device__ __forceinline__ void gemv_pipe(const float* __restrict__ W,
                                          const float* __restrict__ vec,
                                          int rowbase,
                                          float* __restrict__ dst,
                                          const float* __restrict__ add_src) {
    extern __shared__ float4 sbuf[];   // [2][ROWS][C4]
    const int t = threadIdx.x;
    const float* wbase = W + (size_t)rowbase * D + t * 4;

    // Register-cache this thread's slice of the input vector (8 float4).
    const float4* xv = (const float4*)vec;
    float4 xr[NCHUNK];
#pragma unroll
    for (int k = 0; k < NCHUNK; k++) xr[k] = xv[k * C4 + t];

    // Issue one stage: 8 cp.asyncs (one per row), one commit group.
#define ISSUE_STAGE(s)                                                         \
    do {                                                                       \
        const float* _src = wbase + (s) * CHUNK;                               \
        float4* _d = sbuf + ((s) & 1) * STAGE_F4 + t;                          \
        _Pragma("unroll")                                                      \
        for (int _r = 0; _r < ROWS; _r++)                                      \
            cp_async16(_d + _r * C4, _src + (size_t)_r * D);                   \
        cp_commit();                                                           \
    } while (0)

    ISSUE_STAGE(0);

    float acc[ROWS];
#pragma unroll
    for (int r = 0; r < ROWS; r++) acc[r] = 0.f;

#pragma unroll
    for (int ci = 0; ci < NCHUNK; ci++) {
        if (ci + 1 < NCHUNK) {
            ISSUE_STAGE(ci + 1);
            cp_wait<1>();     // this thread's stage-ci group has landed
        } else {
            cp_wait<0>();
        }

        const float4* sb = sbuf + (ci & 1) * STAGE_F4 + t;
        float4 x4 = xr[ci];
#pragma unroll
        for (int r = 0; r < ROWS; r++) {
            float4 w4 = sb[r * C4];
            acc[r] += w4.x * x4.x + w4.y * x4.y + w4.z * x4.z + w4.w * x4.w;
        }
    }
#undef ISSUE_STAGE

    // Reduce: warp shuffle per row, then cross-warp via smem.
#pragma unroll
    for (int r = 0; r < ROWS; r++) {
#pragma unroll
        for (int o = 16; o > 0; o >>= 1)
            acc[r] += __shfl_xor_sync(0xFFFFFFFFu, acc[r], o);
    }

    __shared__ float sred[GTHREADS / 32][ROWS];
    int warp = t >> 5;
    int lane = t & 31;
    if (lane == 0) {
#pragma unroll
        for (int r = 0; r < ROWS; r++) sred[warp][r] = acc[r];
    }
    __syncthreads();
    if (t < ROWS) {
        float s = 0.f;
#pragma unroll
        for (int w = 0; w < GTHREADS / 32; w++) s += sred[w][t];
        int row = rowbase + t;
        dst[row] = add_src ? (add_src[row] + s) : s;
    }
}

// K1: fused Wr/Wk/Wv GEMV. grid.x = 3 * D/ROWS = 3072
__global__ void __launch_bounds__(GTHREADS, 3) gemv3_kernel(const float* __restrict__ Wr,
                                                            const float* __restrict__ Wk,
                                                            const float* __restrict__ Wv) {
    const int blocks_per_mat = D / ROWS;  // 1024
    int mat = blockIdx.x / blocks_per_mat;
    int rowbase = (blockIdx.x % blocks_per_mat) * ROWS;
    const float* W = (mat == 0) ? Wr : ((mat == 1) ? Wk : Wv);
    float* dst = (mat == 0) ? g_rpre : ((mat == 1) ? g_k : g_v);
    gemv_pipe(W, g_x, rowbase, dst, nullptr);
}

// K3: h = x + Wo @ y. grid.x = D/ROWS = 1024
__global__ void __launch_bounds__(GTHREADS, 3) gemv_o_kernel(const float* __restrict__ Wo) {
    int rowbase = blockIdx.x * ROWS;
    gemv_pipe(Wo, g_y, rowbase, g_h, g_x);
}

// ---------------------------------------------------------------------------
// K2: elementwise (decay, RoPE, Kalman gate) -> y
// ---------------------------------------------------------------------------
__global__ void elemwise_kernel(const float* __restrict__ step_pos,
                                const float* __restrict__ state_num,
                                const float* __restrict__ state_den,
                                const float* __restrict__ state_var,
                                const float* __restrict__ raw_decay,
                                const float* __restrict__ pn_param,
                                const float* __restrict__ on_param,
                                const float* __restrict__ W_time) {
    int i = blockIdx.x * 256 + threadIdx.x;
    if (i >= D) return;

    float k = g_k[i];
    float v = g_v[i];
    if (i < 2 * M_TIME) {
        int m = i >> 1;
        float th = step_pos[0] * W_time[m];
        float c, s;
        sincosf(th, &s, &c);
        float v0 = g_v[2 * m];
        float v1 = g_v[2 * m + 1];
        v = (i & 1) ? (v0 * s + v1 * c) : (v0 * c - v1 * s);
    }

    float sp = softplusf(raw_decay[i]);
    float rate = fmaxf(-sp, -30.f);
    float lam = fmaxf(expf(rate), 1e-6f);
    float pn = fminf(fmaxf(softplusf(pn_param[0]), 1e-6f), 1e4f);
    float on = fminf(fmaxf(softplusf(on_param[0]), 1e-6f), 1e4f);

    float sn = state_num[i] * lam;
    float sd = state_den[i] * lam;
    float sv = state_var[i] * lam * lam + pn;

    float r = 1.f / (1.f + expf(-g_rpre[i]));
    float w = expf(fminf(k, 30.f));
    float pred_state = sn / (sd + 1e-6f);
    float msg = w * v;
    float resid = msg - pred_state;
    float obs_var = expf(fminf(-k, 30.f)) * on + 1e-6f;
    float gain = sv / (sv + obs_var);
    gain = fminf(fmaxf(gain, 1e-6f), 1.f - 1e-6f);
    float new_state = pred_state + gain * resid;
    g_y[i] = r * new_state;
}

// ---------------------------------------------------------------------------
// K4: exact KWTA_K-th-largest (radix select) + threshold. 1 block, 1024 thr.
// ---------------------------------------------------------------------------
__global__ void topk_kernel(float* __restrict__ out) {
    __shared__ unsigned hist[256];
    __shared__ unsigned s_prefix;
    __shared__ int s_K;
    __shared__ float s_thresh;

    if (threadIdx.x == 0) { s_prefix = 0u; s_K = KWTA_K; }
    __syncthreads();

    for (int pass = 3; pass >= 0; pass--) {
        if (threadIdx.x < 256) hist[threadIdx.x] = 0u;
        __syncthreads();
        unsigned prefmask = (pass == 3) ? 0u : (0xFFFFFFFFu << ((pass + 1) * 8));
        unsigned pref = s_prefix;
        for (int i = threadIdx.x; i < D; i += 1024) {
            unsigned u = __float_as_uint(g_h[i]);
            unsigned key = (u & 0x80000000u) ? ~u : (u | 0x80000000u);
            if ((key & prefmask) == (pref & prefmask)) {
                atomicAdd(&hist[(key >> (pass * 8)) & 255u], 1u);
            }
        }
        __syncthreads();
        if (threadIdx.x == 0) {
            int K = s_K;
            unsigned cum = 0;
            int b = 255;
            for (; b >= 0; b--) {
                cum += hist[b];
                if ((int)cum >= K) break;
            }
            s_K = K - (int)(cum - hist[b]);
            s_prefix = s_prefix | ((unsigned)b << (pass * 8));
        }
        __syncthreads();
    }

    if (threadIdx.x == 0) {
        unsigned key = s_prefix;
        unsigned u = (key & 0x80000000u) ? (key ^ 0x80000000u) : ~key;
        s_thresh = __uint_as_float(u);
    }
    __syncthreads();

    float th = s_thresh;
    for (int i = threadIdx.x; i < D; i += 1024) {
        float h = g_h[i];
        out[i] = (h >= th) ? h : 0.f;
    }
}

// ---------------------------------------------------------------------------
// Launch
// ---------------------------------------------------------------------------
extern "C" void kernel_launch(void* const* d_in, const int* in_sizes, int n_in,
                              void* d_out, int out_size) {
    const float* x_in      = (const float*)d_in[0];
    const float* step_pos  = (const float*)d_in[1];
    const float* pred      = (const float*)d_in[2];
    const float* state_num = (const float*)d_in[3];
    const float* state_den = (const float*)d_in[4];
    const float* state_var = (const float*)d_in[5];
    const float* Wr        = (const float*)d_in[6];
    const float* Wk        = (const float*)d_in[7];
    const float* Wv        = (const float*)d_in[8];
    const float* Wo        = (const float*)d_in[9];
    const float* raw_decay = (const float*)d_in[10];
    const float* pn_param  = (const float*)d_in[11];
    const float* on_param  = (const float*)d_in[12];
    const float* g_norm    = (const float*)d_in[13];
    const float* W_time    = (const float*)d_in[14];
    float* out = (float*)d_out;

    cudaFuncSetAttribute(gemv3_kernel,
                         cudaFuncAttributeMaxDynamicSharedMemorySize, SMEM_BYTES);
    cudaFuncSetAttribute(gemv_o_kernel,
                         cudaFuncAttributeMaxDynamicSharedMemorySize, SMEM_BYTES);

    rmsnorm_kernel<<<1, 1024>>>(x_in, pred, g_norm);
    gemv3_kernel<<<3 * (D / ROWS), GTHREADS, SMEM_BYTES>>>(Wr, Wk, Wv);
    elemwise_kernel<<<D / 256, 256>>>(step_pos, state_num, state_den, state_var,
                                      raw_decay, pn_param, on_param, W_time);
    gemv_o_kernel<<<D / ROWS, GTHREADS, SMEM_BYTES>>>(Wo);
    topk_kernel<<<1, 1024>>>(out);
}

// round 7
// speedup vs baseline: 1.0548x; 1.0548x over previous
#include <cuda_runtime.h>
#include <math.h>

#define D 8192
#define M_TIME 16
#define KWTA_K (D / 8)
#define ROWS 8
#define GTHREADS 256
#define ROW_F4 (D / 4)                 // 2048 float4 per row
#define SLOTS 8                        // float4 slots per thread per row
#define STAGE_F4 ROW_F4                // one full row per stage (32 KB)
#define SMEM_BYTES (2 * STAGE_F4 * 16) // 64 KB double buffer
#define NPART 8                        // sumsq partial blocks: 8*256*4 = 8192 = D

// Scratch (device globals — no allocation allowed)
__device__ float g_x[D];        // (x_in+pred)*g_norm, UNSCALED by rms factor
__device__ float g_partials[NPART];
__device__ float g_rpre[D];
__device__ float g_k[D];
__device__ float g_v[D];
__device__ float g_y[D];
__device__ float g_h[D];

__device__ __forceinline__ float softplusf(float x) {
    if (x > 20.f) return x;
    if (x < -20.f) return expf(x);
    return log1pf(expf(x));
}

__device__ __forceinline__ void cp_async16(void* smem_dst, const void* gmem_src) {
    unsigned saddr = (unsigned)__cvta_generic_to_shared(smem_dst);
    asm volatile("cp.async.cg.shared.global [%0], [%1], 16;\n"
                 :: "r"(saddr), "l"(gmem_src));
}
__device__ __forceinline__ void cp_commit() {
    asm volatile("cp.async.commit_group;\n");
}
template <int N>
__device__ __forceinline__ void cp_wait() {
    asm volatile("cp.async.wait_group %0;\n" :: "n"(N));
}

// ---------------------------------------------------------------------------
// K0: prep — xg = (x_in+pred)*g_norm, and deterministic sumsq partials.
// 8 blocks x 256 threads; each thread handles exactly one float4 (8*256*4=D).
// ---------------------------------------------------------------------------
__global__ void prep_kernel(const float* __restrict__ x_in,
                            const float* __restrict__ pred,
                            const float* __restrict__ g_norm) {
    int i4 = blockIdx.x * 256 + threadIdx.x;   // float4 index in [0, D/4)
    const float4* xi = (const float4*)x_in;
    const float4* pi = (const float4*)pred;
    const float4* gi = (const float4*)g_norm;
    float4 x4 = xi[i4], p4 = pi[i4], g4 = gi[i4];
    float4 t4 = make_float4(x4.x + p4.x, x4.y + p4.y, x4.z + p4.z, x4.w + p4.w);
    ((float4*)g_x)[i4] = make_float4(t4.x * g4.x, t4.y * g4.y, t4.z * g4.z, t4.w * g4.w);
    float s = t4.x * t4.x + t4.y * t4.y + t4.z * t4.z + t4.w * t4.w;
#pragma unroll
    for (int o = 16; o > 0; o >>= 1) s += __shfl_xor_sync(0xFFFFFFFFu, s, o);
    __shared__ float sw[8];
    if ((threadIdx.x & 31) == 0) sw[threadIdx.x >> 5] = s;
    __syncthreads();
    if (threadIdx.x == 0) {
        float b = sw[0] + sw[1] + sw[2] + sw[3] + sw[4] + sw[5] + sw[6] + sw[7];
        g_partials[blockIdx.x] = b;
    }
}

__device__ __forceinline__ float rms_scale() {
    float ss = 0.f;
#pragma unroll
    for (int i = 0; i < NPART; i++) ss += g_partials[i];
    return rsqrtf(ss / (float)D + 1e-6f);
}

// ---------------------------------------------------------------------------
// Row-sequential barrier-free GEMV pipeline.
// Stage r = entire row (rowbase+r), 32 KB, loaded by 8 cp.asyncs/thread.
// Thread t owns float4 slots (t + 256j), j=0..7, of every row -> consumes
// only smem it wrote -> per-thread cp.async.wait_group is the only sync.
// CTA address stream is purely sequential over its 256 KB slab.
// mode: 0 = dst[row] = scale * dot           (gemv3)
//       1 = dst[row] = scale*g_x[row] + dot  (gemv_o; y already carries scale)
// ---------------------------------------------------------------------------
__device__ __forceinline__ void gemv_pipe(const float* __restrict__ W,
                                          const float* __restrict__ vec,
                                          int rowbase,
                                          float* __restrict__ dst,
                                          int mode) {
    extern __shared__ float4 sbuf[];   // [2][ROW_F4]
    const int t = threadIdx.x;
    const float4* xv = (const float4*)vec;

    float4 xr[SLOTS];
#pragma unroll
    for (int j = 0; j < SLOTS; j++) xr[j] = xv[t + 256 * j];

#define ISSUE_ROW(r)                                                           \
    do {                                                                       \
        const float4* _src = (const float4*)(W + (size_t)(rowbase + (r)) * D) + t; \
        float4* _d = sbuf + ((r) & 1) * STAGE_F4 + t;                          \
        _Pragma("unroll")                                                      \
        for (int _j = 0; _j < SLOTS; _j++)                                     \
            cp_async16(_d + 256 * _j, _src + 256 * _j);                        \
        cp_commit();                                                           \
    } while (0)

    ISSUE_ROW(0);

    float acc[ROWS];
#pragma unroll
    for (int r = 0; r < ROWS; r++) {
        if (r + 1 < ROWS) {
            ISSUE_ROW(r + 1);
            cp_wait<1>();
        } else {
            cp_wait<0>();
        }
        const float4* sb = sbuf + (r & 1) * STAGE_F4 + t;
        float a0 = 0.f, a1 = 0.f;
#pragma unroll
        for (int j = 0; j < SLOTS; j += 2) {
            float4 w0 = sb[256 * j],      x0 = xr[j];
            float4 w1 = sb[256 * (j+1)],  x1 = xr[j+1];
            a0 += w0.x * x0.x + w0.y * x0.y + w0.z * x0.z + w0.w * x0.w;
            a1 += w1.x * x1.x + w1.y * x1.y + w1.z * x1.z + w1.w * x1.w;
        }
        acc[r] = a0 + a1;
    }
#undef ISSUE_ROW

#pragma unroll
    for (int r = 0; r < ROWS; r++) {
#pragma unroll
        for (int o = 16; o > 0; o >>= 1)
            acc[r] += __shfl_xor_sync(0xFFFFFFFFu, acc[r], o);
    }

    __shared__ float sred[GTHREADS / 32][ROWS];
    __shared__ float s_scale;
    int warp = t >> 5;
    int lane = t & 31;
    if (lane == 0) {
#pragma unroll
        for (int r = 0; r < ROWS; r++) sred[warp][r] = acc[r];
    }
    if (t == 0) s_scale = rms_scale();
    __syncthreads();
    if (t < ROWS) {
        float s = 0.f;
#pragma unroll
        for (int w = 0; w < GTHREADS / 32; w++) s += sred[w][t];
        int row = rowbase + t;
        if (mode == 0) dst[row] = s_scale * s;
        else           dst[row] = s_scale * g_x[row] + s;
    }
}

// K1: fused Wr/Wk/Wv GEMV of the (unscaled) xg; scale folded into epilogue.
__global__ void __launch_bounds__(GTHREADS, 3) gemv3_kernel(const float* __restrict__ Wr,
                                                            const float* __restrict__ Wk,
                                                            const float* __restrict__ Wv) {
    const int blocks_per_mat = D / ROWS;  // 1024
    int mat = blockIdx.x / blocks_per_mat;
    int rowbase = (blockIdx.x % blocks_per_mat) * ROWS;
    const float* W = (mat == 0) ? Wr : ((mat == 1) ? Wk : Wv);
    float* dst = (mat == 0) ? g_rpre : ((mat == 1) ? g_k : g_v);
    gemv_pipe(W, g_x, rowbase, dst, 0);
}

// K3: h = scale*xg + Wo @ y  (y already carries scale through the chain)
__global__ void __launch_bounds__(GTHREADS, 3) gemv_o_kernel(const float* __restrict__ Wo) {
    int rowbase = blockIdx.x * ROWS;
    gemv_pipe(Wo, g_y, rowbase, g_h, 1);
}

// ---------------------------------------------------------------------------
// K2: elementwise (decay, RoPE, Kalman gate) -> y
// ---------------------------------------------------------------------------
__global__ void elemwise_kernel(const float* __restrict__ step_pos,
                                const float* __restrict__ state_num,
                                const float* __restrict__ state_den,
                                const float* __restrict__ state_var,
                                const float* __restrict__ raw_decay,
                                const float* __restrict__ pn_param,
                                const float* __restrict__ on_param,
                                const float* __restrict__ W_time) {
    int i = blockIdx.x * 256 + threadIdx.x;
    if (i >= D) return;

    float k = g_k[i];
    float v = g_v[i];
    if (i < 2 * M_TIME) {
        int m = i >> 1;
        float th = step_pos[0] * W_time[m];
        float c, s;
        sincosf(th, &s, &c);
        float v0 = g_v[2 * m];
        float v1 = g_v[2 * m + 1];
        v = (i & 1) ? (v0 * s + v1 * c) : (v0 * c - v1 * s);
    }

    float sp = softplusf(raw_decay[i]);
    float rate = fmaxf(-sp, -30.f);
    float lam = fmaxf(expf(rate), 1e-6f);
    float pn = fminf(fmaxf(softplusf(pn_param[0]), 1e-6f), 1e4f);
    float on = fminf(fmaxf(softplusf(on_param[0]), 1e-6f), 1e4f);

    float sn = state_num[i] * lam;
    float sd = state_den[i] * lam;
    float sv = state_var[i] * lam * lam + pn;

    float r = 1.f / (1.f + expf(-g_rpre[i]));
    float w = expf(fminf(k, 30.f));
    float pred_state = sn / (sd + 1e-6f);
    float msg = w * v;
    float resid = msg - pred_state;
    float obs_var = expf(fminf(-k, 30.f)) * on + 1e-6f;
    float gain = sv / (sv + obs_var);
    gain = fminf(fmaxf(gain, 1e-6f), 1.f - 1e-6f);
    float new_state = pred_state + gain * resid;
    g_y[i] = r * new_state;
}

// ---------------------------------------------------------------------------
// K4: exact KWTA_K-th-largest (radix select) + threshold. 1 block, 1024 thr.
// ---------------------------------------------------------------------------
__global__ void topk_kernel(float* __restrict__ out) {
    __shared__ unsigned hist[256];
    __shared__ unsigned s_prefix;
    __shared__ int s_K;
    __shared__ float s_thresh;

    if (threadIdx.x == 0) { s_prefix = 0u; s_K = KWTA_K; }
    __syncthreads();

    for (int pass = 3; pass >= 0; pass--) {
        if (threadIdx.x < 256) hist[threadIdx.x] = 0u;
        __syncthreads();
        unsigned prefmask = (pass == 3) ? 0u : (0xFFFFFFFFu << ((pass + 1) * 8));
        unsigned pref = s_prefix;
        for (int i = threadIdx.x; i < D; i += 1024) {
            unsigned u = __float_as_uint(g_h[i]);
            unsigned key = (u & 0x80000000u) ? ~u : (u | 0x80000000u);
            if ((key & prefmask) == (pref & prefmask)) {
                atomicAdd(&hist[(key >> (pass * 8)) & 255u], 1u);
            }
        }
        __syncthreads();
        if (threadIdx.x == 0) {
            int K = s_K;
            unsigned cum = 0;
            int b = 255;
            for (; b >= 0; b--) {
                cum += hist[b];
                if ((int)cum >= K) break;
            }
            s_K = K - (int)(cum - hist[b]);
            s_prefix = s_prefix | ((unsigned)b << (pass * 8));
        }
        __syncthreads();
    }

    if (threadIdx.x == 0) {
        unsigned key = s_prefix;
        unsigned u = (key & 0x80000000u) ? (key ^ 0x80000000u) : ~key;
        s_thresh = __uint_as_float(u);
    }
    __syncthreads();

    float th = s_thresh;
    for (int i = threadIdx.x; i < D; i += 1024) {
        float h = g_h[i];
        out[i] = (h >= th) ? h : 0.f;
    }
}

// ---------------------------------------------------------------------------
// Launch
// ---------------------------------------------------------------------------
extern "C" void kernel_launch(void* const* d_in, const int* in_sizes, int n_in,
                              void* d_out, int out_size) {
    const float* x_in      = (const float*)d_in[0];
    const float* step_pos  = (const float*)d_in[1];
    const float* pred      = (const float*)d_in[2];
    const float* state_num = (const float*)d_in[3];
    const float* state_den = (const float*)d_in[4];
    const float* state_var = (const float*)d_in[5];
    const float* Wr        = (const float*)d_in[6];
    const float* Wk        = (const float*)d_in[7];
    const float* Wv        = (const float*)d_in[8];
    const float* Wo        = (const float*)d_in[9];
    const float* raw_decay = (const float*)d_in[10];
    const float* pn_param  = (const float*)d_in[11];
    const float* on_param  = (const float*)d_in[12];
    const float* g_norm    = (const float*)d_in[13];
    const float* W_time    = (const float*)d_in[14];
    float* out = (float*)d_out;

    cudaFuncSetAttribute(gemv3_kernel,
                         cudaFuncAttributeMaxDynamicSharedMemorySize, SMEM_BYTES);
    cudaFuncSetAttribute(gemv_o_kernel,
                         cudaFuncAttributeMaxDynamicSharedMemorySize, SMEM_BYTES);

    prep_kernel<<<NPART, 256>>>(x_in, pred, g_norm);
    gemv3_kernel<<<3 * (D / ROWS), GTHREADS, SMEM_BYTES>>>(Wr, Wk, Wv);
    elemwise_kernel<<<D / 256, 256>>>(step_pos, state_num, state_den, state_var,
                                      raw_decay, pn_param, on_param, W_time);
    gemv_o_kernel<<<D / ROWS, GTHREADS, SMEM_BYTES>>>(Wo);
    topk_kernel<<<1, 1024>>>(out);
}